// round 2
// baseline (speedup 1.0000x reference)
#include <cuda_runtime.h>
#include <cstdint>

#define T_STEPS 2048
#define BATCH   64
#define IN_DIM  128
#define HDIM    256
#define OUT_DIM 128
#define NBLK    128
#define NTHR    256

#define SH_STRIDE 260   // 260 % 32 == 4 -> conflict-free LDS.128 across lanes
#define SX_STRIDE 132   // 132 % 32 == 4
#define SG_STRIDE 9     // gcd(9,32)==1 -> conflict-free scalar access

// smem layout (floats)
#define OFF_H    0                      // 64*260 = 16640
#define OFF_X    16640                  // 64*132 = 8448
#define OFF_WHH  25088                  // 8*256  = 2048
#define OFF_WIH  27136                  // 8*128  = 1024
#define OFF_WOUT 28160                  // 256
#define OFF_G    28416                  // 64*9   = 576
#define OFF_C    28992                  // 128
#define OFF_BS   29120                  // 8
#define SMEM_FLOATS 29128
#define SMEM_BYTES (SMEM_FLOATS * 4)    // 116512

// persistent state (module-scope device memory; no runtime allocation)
__device__ float    g_h[2][BATCH * HDIM];
__device__ unsigned g_flags[NBLK];

__device__ __forceinline__ void fma4(float& acc, float4 a, float4 b) {
    acc += a.x * b.x; acc += a.y * b.y; acc += a.z * b.z; acc += a.w * b.w;
}

// Flag-array grid barrier. All flags start equal (0 on first run; uniform
// value after every completed run), each thread derives targets from the
// initial value of the flag it polls, so the kernel is replay-safe without
// any reset step.
__device__ __forceinline__ void gbar(int tid, int bid, unsigned target) {
    __syncthreads();                    // all block's prior STGs ordered before tid0
    if (tid == 0) {
        __threadfence();                // release: h stores visible gpu-wide first
        *((volatile unsigned*)&g_flags[bid]) = target;
    }
    if (tid < NBLK) {
        while (*((volatile unsigned*)&g_flags[tid]) < target) { __nanosleep(32); }
    }
    __syncthreads();
}

__global__ void __launch_bounds__(NTHR, 1) lstm_persistent_kernel(
    const float* __restrict__ input,   // [T, B, IN]
    const float* __restrict__ W_ih,    // [4H, IN]
    const float* __restrict__ W_hh,    // [4H, H]
    const float* __restrict__ b_ih,    // [4H]
    const float* __restrict__ b_hh,    // [4H]
    const float* __restrict__ W_out,   // [OUT, H]
    const float* __restrict__ b_out,   // [OUT]
    float* __restrict__ out,           // [T,B,OUT] (+ hT[B,H] + cT[B,H] if present)
    int out_size)
{
    extern __shared__ float sm[];
    float* sH    = sm + OFF_H;
    float* sX    = sm + OFF_X;
    float* sWhh  = sm + OFF_WHH;
    float* sWih  = sm + OFF_WIH;
    float* sWout = sm + OFF_WOUT;
    float* sG    = sm + OFF_G;
    float* sC    = sm + OFF_C;
    float* sBias = sm + OFF_BS;

    const int tid = threadIdx.x;
    const int bid = blockIdx.x;

    // per-thread barrier base (all flags uniform at kernel start)
    unsigned base = 0;
    if (tid < NBLK) base = *((volatile unsigned*)&g_flags[tid]);

    // ---- preload weights for this block's 2 hidden columns (m0 = 2*bid) ----
    // gate column jc in [0,8): q = jc>>1 (i,f,g,o), j = jc&1 (which h col)
    for (int i = tid; i < 8 * HDIM; i += NTHR) {
        int jc = i / HDIM, k = i % HDIM;
        int grow = (jc >> 1) * HDIM + 2 * bid + (jc & 1);
        sWhh[jc * HDIM + k] = W_hh[grow * HDIM + k];
    }
    for (int i = tid; i < 8 * IN_DIM; i += NTHR) {
        int jc = i / IN_DIM, k = i % IN_DIM;
        int grow = (jc >> 1) * HDIM + 2 * bid + (jc & 1);
        sWih[jc * IN_DIM + k] = W_ih[grow * IN_DIM + k];
    }
    for (int k = tid; k < HDIM; k += NTHR) sWout[k] = W_out[bid * HDIM + k];
    if (tid < 8) {
        int grow = (tid >> 1) * HDIM + 2 * bid + (tid & 1);
        sBias[tid] = b_ih[grow] + b_hh[grow];
    }
    if (tid < NBLK) sC[tid] = 0.0f;
    // zero our columns of the t=0 h buffer
    if (tid < NBLK) {
        int r = tid & 63, j = tid >> 6;
        g_h[0][r * HDIM + 2 * bid + j] = 0.0f;
    }
    const float bOut = b_out[bid];

    gbar(tid, bid, base + 1);

    const size_t Y_TOTAL = (size_t)T_STEPS * BATCH * OUT_DIM;
    const bool write_tail = (out_size >= (int)(Y_TOTAL + 2 * BATCH * HDIM));

    for (int t = 0; t < T_STEPS; t++) {
        // ---- fill sH <- h_t (L2, bypass L1: other blocks wrote it) ----
        {
            const float* hsrc = g_h[t & 1];
            int r = tid & 63, kq = tid >> 6;               // kq: 64-wide k chunk
            const float4* src = (const float4*)(hsrc + r * HDIM + kq * 64);
            float4* dst = (float4*)(sH + r * SH_STRIDE + kq * 64);
            #pragma unroll
            for (int j = 0; j < 16; j++) dst[j] = __ldcg(&src[j]);
        }
        // ---- fill sX <- x_t ----
        {
            int r = tid & 63, kq = tid >> 6;               // kq: 32-wide k chunk
            const float4* src = (const float4*)(input + (size_t)t * BATCH * IN_DIM
                                                + r * IN_DIM + kq * 32);
            float4* dst = (float4*)(sX + r * SX_STRIDE + kq * 32);
            #pragma unroll
            for (int j = 0; j < 8; j++) dst[j] = src[j];
        }
        __syncthreads();

        if (tid < 128) {
            // ---- gate GEMM: gates[r][jc] = bias + x@Wih^T + h@Whh^T ----
            // thread: rows {l, l+32}, gate cols {2cp, 2cp+1}
            const int l = tid & 31, cp = tid >> 5;
            float a00 = sBias[2 * cp], a01 = sBias[2 * cp + 1];
            float a10 = a00, a11 = a01;

            const float4* xA = (const float4*)(sX + l * SX_STRIDE);
            const float4* xB = (const float4*)(sX + (l + 32) * SX_STRIDE);
            const float4* u0 = (const float4*)(sWih + (2 * cp) * IN_DIM);
            const float4* u1 = (const float4*)(sWih + (2 * cp + 1) * IN_DIM);
            #pragma unroll 4
            for (int kk = 0; kk < IN_DIM / 4; kk++) {
                float4 xa = xA[kk], xb = xB[kk], p0 = u0[kk], p1 = u1[kk];
                fma4(a00, xa, p0); fma4(a01, xa, p1);
                fma4(a10, xb, p0); fma4(a11, xb, p1);
            }

            const float4* hA = (const float4*)(sH + l * SH_STRIDE);
            const float4* hB = (const float4*)(sH + (l + 32) * SH_STRIDE);
            const float4* w0 = (const float4*)(sWhh + (2 * cp) * HDIM);
            const float4* w1 = (const float4*)(sWhh + (2 * cp + 1) * HDIM);
            #pragma unroll 4
            for (int kk = 0; kk < HDIM / 4; kk++) {
                float4 ha = hA[kk], hb = hB[kk], p0 = w0[kk], p1 = w1[kk];
                fma4(a00, ha, p0); fma4(a01, ha, p1);
                fma4(a10, hb, p0); fma4(a11, hb, p1);
            }

            sG[l * SG_STRIDE + 2 * cp]            = a00;
            sG[l * SG_STRIDE + 2 * cp + 1]        = a01;
            sG[(l + 32) * SG_STRIDE + 2 * cp]     = a10;
            sG[(l + 32) * SG_STRIDE + 2 * cp + 1] = a11;
        } else if (t > 0 && tid < 192) {
            // ---- y_{t-1} = h_t @ W_out^T (overlapped with gate GEMM) ----
            int r = tid - 128;
            float acc = bOut;
            const float4* hv = (const float4*)(sH + r * SH_STRIDE);
            const float4* wv = (const float4*)sWout;
            #pragma unroll 4
            for (int kk = 0; kk < HDIM / 4; kk++) fma4(acc, hv[kk], wv[kk]);
            out[(size_t)(t - 1) * BATCH * OUT_DIM + r * OUT_DIM + bid] = acc;
        }
        __syncthreads();

        if (tid < 128) {
            // ---- elementwise LSTM cell for (r, m0+j) ----
            int r = tid & 63, j = tid >> 6;
            float gi = sG[r * SG_STRIDE + 0 + j];
            float gf = sG[r * SG_STRIDE + 2 + j];
            float gg = sG[r * SG_STRIDE + 4 + j];
            float go = sG[r * SG_STRIDE + 6 + j];
            float i_ = 1.0f / (1.0f + __expf(-gi));
            float f_ = 1.0f / (1.0f + __expf(-gf));
            float g_ = tanhf(gg);
            float o_ = 1.0f / (1.0f + __expf(-go));
            float c  = sC[r * 2 + j];
            float cn = f_ * c + i_ * g_;
            float hn = o_ * tanhf(cn);
            sC[r * 2 + j] = cn;
            g_h[(t + 1) & 1][r * HDIM + 2 * bid + j] = hn;
            if (t == T_STEPS - 1 && write_tail) {
                out[Y_TOTAL + r * HDIM + 2 * bid + j] = hn;                 // h_T
                out[Y_TOTAL + BATCH * HDIM + r * HDIM + 2 * bid + j] = cn;  // c_T
            }
        }
        gbar(tid, bid, base + 2 + (unsigned)t);
    }

    // ---- final output row: y_{T-1} from h_T ----
    {
        const float* hsrc = g_h[T_STEPS & 1];
        int r = tid & 63, kq = tid >> 6;
        const float4* src = (const float4*)(hsrc + r * HDIM + kq * 64);
        float4* dst = (float4*)(sH + r * SH_STRIDE + kq * 64);
        #pragma unroll
        for (int j = 0; j < 16; j++) dst[j] = __ldcg(&src[j]);
    }
    __syncthreads();
    if (tid >= 128 && tid < 192) {
        int r = tid - 128;
        float acc = bOut;
        const float4* hv = (const float4*)(sH + r * SH_STRIDE);
        const float4* wv = (const float4*)sWout;
        #pragma unroll 4
        for (int kk = 0; kk < HDIM / 4; kk++) fma4(acc, hv[kk], wv[kk]);
        out[(size_t)(T_STEPS - 1) * BATCH * OUT_DIM + r * OUT_DIM + bid] = acc;
    }
}

extern "C" void kernel_launch(void* const* d_in, const int* in_sizes, int n_in,
                              void* d_out, int out_size) {
    const float* input = (const float*)d_in[0];
    const float* W_ih  = (const float*)d_in[1];
    const float* W_hh  = (const float*)d_in[2];
    const float* b_ih  = (const float*)d_in[3];
    const float* b_hh  = (const float*)d_in[4];
    const float* W_out = (const float*)d_in[5];
    const float* b_out = (const float*)d_in[6];
    float* out = (float*)d_out;
    (void)in_sizes; (void)n_in;

    cudaFuncSetAttribute(lstm_persistent_kernel,
                         cudaFuncAttributeMaxDynamicSharedMemorySize, SMEM_BYTES);
    lstm_persistent_kernel<<<NBLK, NTHR, SMEM_BYTES>>>(
        input, W_ih, W_hh, b_ih, b_hh, W_out, b_out, out, out_size);
}

// round 3
// speedup vs baseline: 1.0447x; 1.0447x over previous
#include <cuda_runtime.h>
#include <cstdint>

#define T_STEPS 2048
#define BATCH   64
#define IN_DIM  128
#define HDIM    256
#define OUT_DIM 128
#define NBLK    128
#define NTHR    256
#define KTOT    384          // IN_DIM + HDIM (unified k-space: x then h)
#define SA_STR  388          // 388 % 32 == 4 -> conflict-free strided LDS.128
#define SP_STR  12           // 12*l mod 32 distinct within 8-lane phase

// smem layout (floats)
#define OFF_A     0                       // 64 * 388 = 24832 (activations x|h)
#define OFF_W     24832                   // 8 * 384  = 3072  (gate weights)
#define OFF_WOUT  27904                   // 256
#define OFF_P     28160                   // 4 * 64 * 12 = 3072 (split-K partials)
#define OFF_C     31232                   // 128 (cell state)
#define OFF_BS    31360                   // 8  (gate biases)
#define OFF_BASE  31368                   // 1  (barrier base)
#define SMEM_FLOATS 31372
#define SMEM_BYTES (SMEM_FLOATS * 4)      // 125488

// persistent state (module-scope; no runtime allocation)
__device__ float g_h[2][BATCH * HDIM];
struct Flag { unsigned v; unsigned pad[31]; };   // one L2 line per flag
__device__ Flag g_flags[NBLK];

__device__ __forceinline__ void fma4(float& acc, float4 a, float4 b) {
    acc += a.x * b.x; acc += a.y * b.y; acc += a.z * b.z; acc += a.w * b.w;
}

// Flag-array grid barrier: one padded line per block, only warp 0 polls.
// Flags are uniform at kernel start (0 first run, base+2049 after each run);
// targets derived from the initial value -> replay-safe with no reset.
__device__ __forceinline__ void gbar(int tid, int bid, unsigned target) {
    __syncthreads();                  // block's prior stores ordered before tid0
    if (tid == 0) {
        __threadfence();              // release: h stores visible gpu-wide first
        *((volatile unsigned*)&g_flags[bid].v) = target;
    }
    if (tid < 32) {
        #pragma unroll
        for (int i = 0; i < 4; i++) {
            volatile unsigned* p = &g_flags[tid + i * 32].v;
            while (*p < target) { __nanosleep(32); }
        }
        __threadfence();              // acquire side
    }
    __syncthreads();
}

__global__ void __launch_bounds__(NTHR, 1) lstm_persistent_kernel(
    const float* __restrict__ input,   // [T, B, IN]
    const float* __restrict__ W_ih,    // [4H, IN]
    const float* __restrict__ W_hh,    // [4H, H]
    const float* __restrict__ b_ih,    // [4H]
    const float* __restrict__ b_hh,    // [4H]
    const float* __restrict__ W_out,   // [OUT, H]
    const float* __restrict__ b_out,   // [OUT]
    float* __restrict__ out,
    int out_size)
{
    extern __shared__ float sm[];
    float* sA    = sm + OFF_A;
    float* sW    = sm + OFF_W;
    float* sWout = sm + OFF_WOUT;
    float* sP    = sm + OFF_P;
    float* sC    = sm + OFF_C;
    float* sBias = sm + OFF_BS;
    float* sBase = sm + OFF_BASE;

    const int tid = threadIdx.x;
    const int bid = blockIdx.x;

    if (tid == 0)
        sBase[0] = __uint_as_float(*((volatile unsigned*)&g_flags[bid].v));

    // ---- preload weights: unified [8 gate-cols x 384 k] (x part then h part) ----
    for (int i = tid; i < 8 * KTOT; i += NTHR) {
        int c = i / KTOT, k = i % KTOT;
        int grow = (c >> 1) * HDIM + 2 * bid + (c & 1);
        sW[i] = (k < IN_DIM) ? W_ih[grow * IN_DIM + k]
                             : W_hh[grow * HDIM + (k - IN_DIM)];
    }
    for (int k = tid; k < HDIM; k += NTHR) sWout[k] = W_out[bid * HDIM + k];
    if (tid < 8) {
        int grow = (tid >> 1) * HDIM + 2 * bid + (tid & 1);
        sBias[tid] = b_ih[grow] + b_hh[grow];
    }
    if (tid < 128) {
        sC[tid] = 0.0f;
        int r = tid & 63, j = tid >> 6;
        g_h[0][r * HDIM + 2 * bid + j] = 0.0f;
    }
    // prefetch x_0 into sA cols [0,128)
    {
        int r = tid & 63, kq = tid >> 6;
        const float4* src = (const float4*)(input + (size_t)0 + r * IN_DIM + kq * 32);
        float4* dst = (float4*)(sA + r * SA_STR + kq * 32);
        #pragma unroll
        for (int j = 0; j < 8; j++) dst[j] = src[j];
    }
    const float bOut = b_out[bid];
    __syncthreads();
    const unsigned base = __float_as_uint(sBase[0]);

    gbar(tid, bid, base + 1);

    const size_t Y_TOTAL = (size_t)T_STEPS * BATCH * OUT_DIM;
    const bool write_tail = (out_size >= (int)(Y_TOTAL + 2 * BATCH * HDIM));

    // GEMM thread mapping (constant across steps)
    const int slot = tid & 63;            // 64 output slots
    const int kg   = tid >> 6;            // 4 split-K groups
    const int r0   = slot & 31;           // rows r0, r0+32
    const int colq = (slot >> 5) << 2;    // gate-col quad: 0 or 4
    const int kbase = kg * 96;

    for (int t = 0; t < T_STEPS; t++) {
        // ---- phase 1: fill sA h-region <- h_t (L2, bypass L1) ----
        {
            const float* hsrc = g_h[t & 1];
            int r = tid & 63, kq = tid >> 6;
            const float4* src = (const float4*)(hsrc + r * HDIM + kq * 64);
            float4* dst = (float4*)(sA + r * SA_STR + IN_DIM + kq * 64);
            #pragma unroll
            for (int j = 0; j < 16; j++) dst[j] = __ldcg(&src[j]);
        }
        __syncthreads();

        // ---- phase 2: gate GEMM, 8 warps, 2r x 4c tiles, split-K=4 ----
        {
            const float4* a0 = (const float4*)(sA + r0 * SA_STR + kbase);
            const float4* a1 = (const float4*)(sA + (r0 + 32) * SA_STR + kbase);
            const float4* w0 = (const float4*)(sW + (colq + 0) * KTOT + kbase);
            const float4* w1 = (const float4*)(sW + (colq + 1) * KTOT + kbase);
            const float4* w2 = (const float4*)(sW + (colq + 2) * KTOT + kbase);
            const float4* w3 = (const float4*)(sW + (colq + 3) * KTOT + kbase);
            float acc0 = 0.f, acc1 = 0.f, acc2 = 0.f, acc3 = 0.f;
            float acc4 = 0.f, acc5 = 0.f, acc6 = 0.f, acc7 = 0.f;
            #pragma unroll 2
            for (int kk = 0; kk < 24; kk++) {
                float4 xa = a0[kk], xb = a1[kk];
                float4 v0 = w0[kk], v1 = w1[kk], v2 = w2[kk], v3 = w3[kk];
                fma4(acc0, xa, v0); fma4(acc1, xa, v1);
                fma4(acc2, xa, v2); fma4(acc3, xa, v3);
                fma4(acc4, xb, v0); fma4(acc5, xb, v1);
                fma4(acc6, xb, v2); fma4(acc7, xb, v3);
            }
            float4* ps = (float4*)(sP + kg * 768 + slot * SP_STR);
            ps[0] = make_float4(acc0, acc1, acc2, acc3);   // rows r0,   cols quad
            ps[1] = make_float4(acc4, acc5, acc6, acc7);   // rows r0+32
        }
        __syncthreads();

        // ---- phase 3: elementwise cell (warps 0-3)  ||  y_{t-1} (warps 4-7) ----
        if (tid < 128) {
            int r = tid & 63, j = tid >> 6;
            int sl0 = (r & 31) * SP_STR;            // quad 0 (cols 0-3)
            int sl1 = sl0 + 32 * SP_STR;            // quad 1 (cols 4-7)
            int rh  = (r >> 5) * 4;
            float gi = sBias[0 + j], gf = sBias[2 + j];
            float gg = sBias[4 + j], go = sBias[6 + j];
            #pragma unroll
            for (int g = 0; g < 4; g++) {
                const float* p = sP + g * 768;
                gi += p[sl0 + rh + j];
                gf += p[sl0 + rh + 2 + j];
                gg += p[sl1 + rh + j];
                go += p[sl1 + rh + 2 + j];
            }
            float i_ = 1.0f / (1.0f + __expf(-gi));
            float f_ = 1.0f / (1.0f + __expf(-gf));
            float g_ = tanhf(gg);
            float o_ = 1.0f / (1.0f + __expf(-go));
            float c  = sC[r * 2 + j];
            float cn = f_ * c + i_ * g_;
            float hn = o_ * tanhf(cn);
            sC[r * 2 + j] = cn;
            g_h[(t + 1) & 1][r * HDIM + 2 * bid + j] = hn;
            if (t == T_STEPS - 1 && write_tail) {
                out[Y_TOTAL + r * HDIM + 2 * bid + j] = hn;                 // h_T
                out[Y_TOTAL + BATCH * HDIM + r * HDIM + 2 * bid + j] = cn;  // c_T
            }
        } else {
            // y_{t-1} = h_t @ W_out^T for col bid; 2 threads per row (k halves)
            int r2 = tid - 128;
            int row = r2 >> 1, half = r2 & 1;
            float acc = 0.f;
            const float4* hv = (const float4*)(sA + row * SA_STR + IN_DIM + half * 128);
            const float4* wv = (const float4*)(sWout + half * 128);
            #pragma unroll 4
            for (int kk = 0; kk < 32; kk++) fma4(acc, hv[kk], wv[kk]);
            acc += __shfl_xor_sync(0xffffffffu, acc, 1);
            if (t > 0 && half == 0)
                out[(size_t)(t - 1) * BATCH * OUT_DIM + row * OUT_DIM + bid] = acc + bOut;
        }

        // ---- phase 4: prefetch x_{t+1} (independent of recurrence) ----
        if (t + 1 < T_STEPS) {
            int r = tid & 63, kq = tid >> 6;
            const float4* src = (const float4*)(input + (size_t)(t + 1) * BATCH * IN_DIM
                                                + r * IN_DIM + kq * 32);
            float4* dst = (float4*)(sA + r * SA_STR + kq * 32);
            #pragma unroll
            for (int j = 0; j < 8; j++) dst[j] = src[j];
        }

        gbar(tid, bid, base + 2 + (unsigned)t);
    }

    // ---- tail: y_{T-1} from h_T ----
    {
        const float* hsrc = g_h[T_STEPS & 1];
        int r = tid & 63, kq = tid >> 6;
        const float4* src = (const float4*)(hsrc + r * HDIM + kq * 64);
        float4* dst = (float4*)(sA + r * SA_STR + IN_DIM + kq * 64);
        #pragma unroll
        for (int j = 0; j < 16; j++) dst[j] = __ldcg(&src[j]);
    }
    __syncthreads();
    if (tid >= 128) {
        int r2 = tid - 128;
        int row = r2 >> 1, half = r2 & 1;
        float acc = 0.f;
        const float4* hv = (const float4*)(sA + row * SA_STR + IN_DIM + half * 128);
        const float4* wv = (const float4*)(sWout + half * 128);
        #pragma unroll 4
        for (int kk = 0; kk < 32; kk++) fma4(acc, hv[kk], wv[kk]);
        acc += __shfl_xor_sync(0xffffffffu, acc, 1);
        if (half == 0)
            out[(size_t)(T_STEPS - 1) * BATCH * OUT_DIM + row * OUT_DIM + bid] = acc + bOut;
    }
}

extern "C" void kernel_launch(void* const* d_in, const int* in_sizes, int n_in,
                              void* d_out, int out_size) {
    const float* input = (const float*)d_in[0];
    const float* W_ih  = (const float*)d_in[1];
    const float* W_hh  = (const float*)d_in[2];
    const float* b_ih  = (const float*)d_in[3];
    const float* b_hh  = (const float*)d_in[4];
    const float* W_out = (const float*)d_in[5];
    const float* b_out = (const float*)d_in[6];
    float* out = (float*)d_out;
    (void)in_sizes; (void)n_in;

    cudaFuncSetAttribute(lstm_persistent_kernel,
                         cudaFuncAttributeMaxDynamicSharedMemorySize, SMEM_BYTES);
    lstm_persistent_kernel<<<NBLK, NTHR, SMEM_BYTES>>>(
        input, W_ih, W_hh, b_ih, b_hh, W_out, b_out, out, out_size);
}

// round 4
// speedup vs baseline: 1.4368x; 1.3754x over previous
#include <cuda_runtime.h>
#include <cstdint>

#define T_STEPS 2048
#define BATCH   64
#define IN_DIM  128
#define HDIM    256
#define OUT_DIM 128
#define NBLK    128
#define NTHR    256
#define KTOT    384

#define SA_STR  516          // 516 % 32 == 4 -> conflict-free strided LDS.128
#define XB0     0            // x buffer 0 (cols 0..127 of row)
#define XB1     128          // x buffer 1
#define HOFF    256          // h region (cols 256..511)
#define SP_STR  12

// smem layout (floats)
#define OFF_A     0                       // 64 * 516 = 33024
#define OFF_W     33024                   // 8 * 384  = 3072
#define OFF_WOUT  36096                   // 256
#define OFF_P     36352                   // 4 * 64 * 12 = 3072
#define OFF_C     39424                   // 128
#define OFF_BS    39552                   // 8
#define OFF_BASE  39560                   // 1
#define SMEM_FLOATS 39561
#define SMEM_BYTES (SMEM_FLOATS * 4)      // 158244

__device__ float g_h[2][BATCH * HDIM];
struct Flag { unsigned v; unsigned pad[31]; };   // one 128B line per flag
__device__ Flag g_flags[NBLK];

__device__ __forceinline__ void fma4(float& acc, float4 a, float4 b) {
    acc += a.x * b.x; acc += a.y * b.y; acc += a.z * b.z; acc += a.w * b.w;
}

// init-time grid barrier (pure spin, parallel poll, no nanosleep)
__device__ __forceinline__ void gbar_init(int tid, int bid, unsigned target) {
    __syncthreads();
    if (tid == 0) {
        __threadfence();
        *((volatile unsigned*)&g_flags[bid].v) = target;
    }
    if (tid < NBLK) {
        volatile unsigned* p = &g_flags[tid].v;
        while (*p < target) { }
        __threadfence();
    }
    __syncthreads();
}

__global__ void __launch_bounds__(NTHR, 1) lstm_persistent_kernel(
    const float* __restrict__ input,   // [T, B, IN]
    const float* __restrict__ W_ih,    // [4H, IN]
    const float* __restrict__ W_hh,    // [4H, H]
    const float* __restrict__ b_ih,    // [4H]
    const float* __restrict__ b_hh,    // [4H]
    const float* __restrict__ W_out,   // [OUT, H]
    const float* __restrict__ b_out,   // [OUT]
    float* __restrict__ out,
    int out_size)
{
    extern __shared__ float sm[];
    float* sA    = sm + OFF_A;
    float* sW    = sm + OFF_W;
    float* sWout = sm + OFF_WOUT;
    float* sP    = sm + OFF_P;
    float* sC    = sm + OFF_C;
    float* sBias = sm + OFF_BS;
    float* sBase = sm + OFF_BASE;

    const int tid = threadIdx.x;
    const int bid = blockIdx.x;

    if (tid == 0)
        sBase[0] = __uint_as_float(*((volatile unsigned*)&g_flags[bid].v));

    // ---- preload weights: unified [8 gate-cols x 384] (x part then h part) ----
    for (int i = tid; i < 8 * KTOT; i += NTHR) {
        int c = i / KTOT, k = i % KTOT;
        int grow = (c >> 1) * HDIM + 2 * bid + (c & 1);
        sW[i] = (k < IN_DIM) ? W_ih[grow * IN_DIM + k]
                             : W_hh[grow * HDIM + (k - IN_DIM)];
    }
    for (int k = tid; k < HDIM; k += NTHR) sWout[k] = W_out[bid * HDIM + k];
    if (tid < 8) {
        int grow = (tid >> 1) * HDIM + 2 * bid + (tid & 1);
        sBias[tid] = b_ih[grow] + b_hh[grow];
    }
    if (tid < 128) {
        sC[tid] = 0.0f;
        int r = tid & 63, j = tid >> 6;
        g_h[0][r * HDIM + 2 * bid + j] = 0.0f;
    }
    // prefetch x_0 into x-buffer 0
    {
        int r = tid & 63, kq = tid >> 6;
        const float4* src = (const float4*)(input + r * IN_DIM + kq * 32);
        float4* dst = (float4*)(sA + r * SA_STR + XB0 + kq * 32);
        #pragma unroll
        for (int j = 0; j < 8; j++) dst[j] = src[j];
    }
    const float bOut = b_out[bid];
    __syncthreads();
    const unsigned base = __float_as_uint(sBase[0]);

    gbar_init(tid, bid, base + 1);

    const size_t Y_TOTAL = (size_t)T_STEPS * BATCH * OUT_DIM;
    const bool write_tail = (out_size >= (int)(Y_TOTAL + 2 * BATCH * HDIM));

    // GEMM mapping (constant across steps)
    const int slot = tid & 63;
    const int kg   = tid >> 6;
    const int r0   = slot & 31;
    const int colq = (slot >> 5) << 2;
    const int fr   = tid & 63;            // fill row
    const int fq   = tid >> 6;            // fill quarter

    for (int t = 0; t < T_STEPS; t++) {
        const int xo  = (t & 1) ? XB1 : XB0;        // x buffer for this step
        const int xn  = (t & 1) ? XB0 : XB1;        // x buffer for next step

        // ---- A: stage x_{t+1} in registers (HBM latency hides under B/C) ----
        float4 xreg[8];
        if (t + 1 < T_STEPS) {
            const float4* src = (const float4*)(input + (size_t)(t + 1) * BATCH * IN_DIM
                                                + fr * IN_DIM + fq * 32);
            #pragma unroll
            for (int j = 0; j < 8; j++) xreg[j] = __ldcg(&src[j]);
        }

        // ---- B: fill sA h-region <- h_t (L2) ----
        {
            const float* hsrc = g_h[t & 1];
            const float4* src = (const float4*)(hsrc + fr * HDIM + fq * 64);
            float4* dst = (float4*)(sA + fr * SA_STR + HOFF + fq * 64);
            #pragma unroll
            for (int j = 0; j < 16; j++) dst[j] = __ldcg(&src[j]);
        }

        // ---- C: x-part GEMM (K = 128), overlapped with h LDGs ----
        float acc0 = 0.f, acc1 = 0.f, acc2 = 0.f, acc3 = 0.f;
        float acc4 = 0.f, acc5 = 0.f, acc6 = 0.f, acc7 = 0.f;
        {
            const float4* a0 = (const float4*)(sA + r0 * SA_STR + xo + kg * 32);
            const float4* a1 = (const float4*)(sA + (r0 + 32) * SA_STR + xo + kg * 32);
            const float4* w0 = (const float4*)(sW + (colq + 0) * KTOT + kg * 32);
            const float4* w1 = (const float4*)(sW + (colq + 1) * KTOT + kg * 32);
            const float4* w2 = (const float4*)(sW + (colq + 2) * KTOT + kg * 32);
            const float4* w3 = (const float4*)(sW + (colq + 3) * KTOT + kg * 32);
            #pragma unroll
            for (int kk = 0; kk < 8; kk++) {
                float4 xa = a0[kk], xb = a1[kk];
                float4 v0 = w0[kk], v1 = w1[kk], v2 = w2[kk], v3 = w3[kk];
                fma4(acc0, xa, v0); fma4(acc1, xa, v1);
                fma4(acc2, xa, v2); fma4(acc3, xa, v3);
                fma4(acc4, xb, v0); fma4(acc5, xb, v1);
                fma4(acc6, xb, v2); fma4(acc7, xb, v3);
            }
        }

        // ---- D: store staged x_{t+1}; sync ----
        if (t + 1 < T_STEPS) {
            float4* dst = (float4*)(sA + fr * SA_STR + xn + fq * 32);
            #pragma unroll
            for (int j = 0; j < 8; j++) dst[j] = xreg[j];
        }
        __syncthreads();

        // ---- E: h-part GEMM (K = 256) ----
        {
            const float4* a0 = (const float4*)(sA + r0 * SA_STR + HOFF + kg * 64);
            const float4* a1 = (const float4*)(sA + (r0 + 32) * SA_STR + HOFF + kg * 64);
            const float4* w0 = (const float4*)(sW + (colq + 0) * KTOT + IN_DIM + kg * 64);
            const float4* w1 = (const float4*)(sW + (colq + 1) * KTOT + IN_DIM + kg * 64);
            const float4* w2 = (const float4*)(sW + (colq + 2) * KTOT + IN_DIM + kg * 64);
            const float4* w3 = (const float4*)(sW + (colq + 3) * KTOT + IN_DIM + kg * 64);
            #pragma unroll 4
            for (int kk = 0; kk < 16; kk++) {
                float4 xa = a0[kk], xb = a1[kk];
                float4 v0 = w0[kk], v1 = w1[kk], v2 = w2[kk], v3 = w3[kk];
                fma4(acc0, xa, v0); fma4(acc1, xa, v1);
                fma4(acc2, xa, v2); fma4(acc3, xa, v3);
                fma4(acc4, xb, v0); fma4(acc5, xb, v1);
                fma4(acc6, xb, v2); fma4(acc7, xb, v3);
            }
            float4* ps = (float4*)(sP + kg * 768 + slot * SP_STR);
            ps[0] = make_float4(acc0, acc1, acc2, acc3);
            ps[1] = make_float4(acc4, acc5, acc6, acc7);
        }
        __syncthreads();

        const unsigned tgt = base + 2 + (unsigned)t;

        // ---- F: cell (warps 0-3, early flag release) || y_{t-1} (warps 4-7) ----
        if (tid < 128) {
            int r = tid & 63, j = tid >> 6;
            int sl0 = (r & 31) * SP_STR;
            int sl1 = sl0 + 32 * SP_STR;
            int rh  = (r >> 5) * 4;
            float gi = sBias[0 + j], gf = sBias[2 + j];
            float gg = sBias[4 + j], go = sBias[6 + j];
            #pragma unroll
            for (int g = 0; g < 4; g++) {
                const float* p = sP + g * 768;
                gi += p[sl0 + rh + j];
                gf += p[sl0 + rh + 2 + j];
                gg += p[sl1 + rh + j];
                go += p[sl1 + rh + 2 + j];
            }
            float i_ = 1.0f / (1.0f + __expf(-gi));
            float f_ = 1.0f / (1.0f + __expf(-gf));
            float g_ = tanhf(gg);
            float o_ = 1.0f / (1.0f + __expf(-go));
            float c  = sC[r * 2 + j];
            float cn = f_ * c + i_ * g_;
            float hn = o_ * tanhf(cn);
            sC[r * 2 + j] = cn;
            g_h[(t + 1) & 1][r * HDIM + 2 * bid + j] = hn;
            if (t == T_STEPS - 1 && write_tail) {
                out[Y_TOTAL + r * HDIM + 2 * bid + j] = hn;                 // h_T
                out[Y_TOTAL + BATCH * HDIM + r * HDIM + 2 * bid + j] = cn;  // c_T
            }
            asm volatile("bar.sync 1, 128;" ::: "memory");
            if (tid == 0) {
                __threadfence();
                *((volatile unsigned*)&g_flags[bid].v) = tgt;
            }
        } else {
            int r2 = tid - 128;
            int row = r2 >> 1, half = r2 & 1;
            float acc = 0.f;
            const float4* hv = (const float4*)(sA + row * SA_STR + HOFF + half * 128);
            const float4* wv = (const float4*)(sWout + half * 128);
            #pragma unroll 4
            for (int kk = 0; kk < 32; kk++) fma4(acc, hv[kk], wv[kk]);
            acc += __shfl_xor_sync(0xffffffffu, acc, 1);
            if (t > 0 && half == 0)
                out[(size_t)(t - 1) * BATCH * OUT_DIM + row * OUT_DIM + bid] = acc + bOut;
        }

        // ---- G: poll (pure spin, 128 parallel pollers) ----
        if (tid < 128) {
            volatile unsigned* p = &g_flags[tid].v;
            while (*p < tgt) { }
            __threadfence();
        }
        __syncthreads();
    }

    // ---- tail: y_{T-1} from h_T ----
    {
        const float* hsrc = g_h[T_STEPS & 1];
        const float4* src = (const float4*)(hsrc + fr * HDIM + fq * 64);
        float4* dst = (float4*)(sA + fr * SA_STR + HOFF + fq * 64);
        #pragma unroll
        for (int j = 0; j < 16; j++) dst[j] = __ldcg(&src[j]);
    }
    __syncthreads();
    if (tid >= 128) {
        int r2 = tid - 128;
        int row = r2 >> 1, half = r2 & 1;
        float acc = 0.f;
        const float4* hv = (const float4*)(sA + row * SA_STR + HOFF + half * 128);
        const float4* wv = (const float4*)(sWout + half * 128);
        #pragma unroll 4
        for (int kk = 0; kk < 32; kk++) fma4(acc, hv[kk], wv[kk]);
        acc += __shfl_xor_sync(0xffffffffu, acc, 1);
        if (half == 0)
            out[(size_t)(T_STEPS - 1) * BATCH * OUT_DIM + row * OUT_DIM + bid] = acc + bOut;
    }
}

extern "C" void kernel_launch(void* const* d_in, const int* in_sizes, int n_in,
                              void* d_out, int out_size) {
    const float* input = (const float*)d_in[0];
    const float* W_ih  = (const float*)d_in[1];
    const float* W_hh  = (const float*)d_in[2];
    const float* b_ih  = (const float*)d_in[3];
    const float* b_hh  = (const float*)d_in[4];
    const float* W_out = (const float*)d_in[5];
    const float* b_out = (const float*)d_in[6];
    float* out = (float*)d_out;
    (void)in_sizes; (void)n_in;

    cudaFuncSetAttribute(lstm_persistent_kernel,
                         cudaFuncAttributeMaxDynamicSharedMemorySize, SMEM_BYTES);
    lstm_persistent_kernel<<<NBLK, NTHR, SMEM_BYTES>>>(
        input, W_ih, W_hh, b_ih, b_hh, W_out, b_out, out, out_size);
}